// round 9
// baseline (speedup 1.0000x reference)
#include <cuda_runtime.h>
#include <cuda_fp16.h>
#include <cstdint>

// Problem constants
#define VOCAB 131072
#define EMB   128
#define HID   256
#define OUT_N 128
#define BATCH 256
#define SEQ_T 512

#define N_RNN_CTAS 32
#define N_PRE_CTAS 116
#define N_VBLK     256   // virtual pre-blocks (512 tokens each)

// Scratch (device globals; no allocations allowed)
__device__ __half g_pre[(size_t)SEQ_T * BATCH * HID];  // [T][B][HID] fp16, includes b_ih+b_hh
__device__ float  g_hT[BATCH * HID];                   // final hidden state fp32
__device__ int    g_x_is64;                            // 1 if x buffer is int64, else 0
__device__ int    g_flag[SEQ_T];                       // pre[t] ready flags
__device__ int    g_wq;                                // work-steal queue head
__device__ int    g_vb_done;                           // completed virtual blocks
__device__ int    g_pre_done;                          // all pre work finished

// ---------------------------------------------------------------------------
__device__ __forceinline__ void mma16816(float c[4],
                                         unsigned a0, unsigned a1, unsigned a2, unsigned a3,
                                         unsigned b0, unsigned b1) {
    asm volatile(
        "mma.sync.aligned.m16n8k16.row.col.f32.f16.f16.f32 "
        "{%0,%1,%2,%3}, {%4,%5,%6,%7}, {%8,%9}, {%0,%1,%2,%3};\n"
        : "+f"(c[0]), "+f"(c[1]), "+f"(c[2]), "+f"(c[3])
        : "r"(a0), "r"(a1), "r"(a2), "r"(a3), "r"(b0), "r"(b1));
}

__device__ __forceinline__ void ldsm2(unsigned& b0, unsigned& b1, unsigned addr) {
    asm volatile("ldmatrix.sync.aligned.m8n8.x2.shared.b16 {%0,%1}, [%2];"
                 : "=r"(b0), "=r"(b1)
                 : "r"(addr));
}

__device__ __forceinline__ float tanh_approx(float x) {
    float y;
    asm("tanh.approx.f32 %0, %1;" : "=f"(y) : "f"(x));
    return y;
}

// accurate tanh (final step only): 1 - 2/(e^{2x}+1)
__device__ __forceinline__ float tanh_fast(float x) {
    float xx = fminf(fmaxf(x, -15.0f), 15.0f);
    float e = __expf(xx + xx);
    float d = e + 1.0f;
    float r = __uint_as_float(0x7EF311C3u - __float_as_uint(d));
    r = r * (2.0f - d * r);
    r = r * (2.0f - d * r);
    return fmaf(-2.0f, r, 1.0f);
}

__device__ __forceinline__ int ld_acquire(const int* p) {
    int v;
    asm volatile("ld.acquire.gpu.b32 %0, [%1];" : "=r"(v) : "l"(p) : "memory");
    return v;
}
__device__ __forceinline__ int ld_relaxed(const int* p) {
    int v;
    asm volatile("ld.relaxed.gpu.b32 %0, [%1];" : "=r"(v) : "l"(p) : "memory");
    return v;
}
__device__ __forceinline__ void st_release(int* p, int v) {
    asm volatile("st.release.gpu.b32 [%0], %1;" :: "l"(p), "r"(v) : "memory");
}

// ---------------------------------------------------------------------------
// Kernel 0: detect x dtype + reset producer/consumer state.
// Reads odd words 1..4095 (first 16KB region — in-bounds for both layouts).
// ---------------------------------------------------------------------------
__global__ void k_detect_x64(const unsigned* __restrict__ xw) {
    __shared__ int s_any;
    if (threadIdx.x == 0) s_any = 0;
    __syncthreads();
    unsigned acc = 0;
    for (int i = threadIdx.x; i < 2048; i += 256)
        acc |= xw[2 * i + 1];
    if (acc) atomicOr(&s_any, 1);
    for (int i = threadIdx.x; i < SEQ_T; i += 256) g_flag[i] = 0;
    __syncthreads();
    if (threadIdx.x == 0) {
        g_x_is64 = (s_any == 0) ? 1 : 0;
        g_wq = 0; g_vb_done = 0; g_pre_done = 0;
    }
}

__device__ __forceinline__ int load_index(const unsigned* xw, int pos) {
    return (int)(g_x_is64 ? xw[2 * pos] : xw[pos]);
}

// ---------------------------------------------------------------------------
// Fused kernel: grid 148. CTAs 0..31: RNN consumers (8 batch rows each).
// CTAs 32..147: pre producers (work-steal 256 vblocks, publish flags).
// ---------------------------------------------------------------------------
#define K1_ASTRIDE 136
#define K2_WSTRIDE 264
#define PSTRIDE    264
// Wsm 135168 + Hbuf 8448 + Pstage 8448 = 152064
#define FUSED_SMEM_BYTES ((256 * K2_WSTRIDE + 2 * 8 * K2_WSTRIDE + 2 * 8 * PSTRIDE) * 2)

__global__ __launch_bounds__(256, 1) void k_main(const unsigned* __restrict__ xw,
                                                 const float* __restrict__ emb,
                                                 const float* __restrict__ W_ih,
                                                 const float* __restrict__ W_hh,
                                                 const float* __restrict__ b_ih,
                                                 const float* __restrict__ b_hh) {
    extern __shared__ char smem[];
    const int tid  = threadIdx.x;
    const int wid  = tid >> 5;
    const int lane = tid & 31;
    const int r    = lane >> 2;
    const int cq   = lane & 3;

    if (blockIdx.x < N_RNN_CTAS) {
        // =================== RNN consumer role ===================
        __half (*Wsm)[K2_WSTRIDE] = reinterpret_cast<__half(*)[K2_WSTRIDE]>(smem);
        __half* Hbuf   = reinterpret_cast<__half*>(smem + 256 * K2_WSTRIDE * 2);
        __half* Pstage = Hbuf + 2 * 8 * K2_WSTRIDE;   // [2][8][PSTRIDE]

        const int ms = wid * 32;
        const int b0 = blockIdx.x * 8;

        for (int i = tid; i < 256 * 256 / 4; i += 256) {
            int m  = i >> 6;
            int k4 = i & 63;
            float4 v = reinterpret_cast<const float4*>(W_hh)[i];
            __half2* dst = reinterpret_cast<__half2*>(&Wsm[m][k4 * 4]);
            dst[0] = __floats2half2_rn(v.x, v.y);
            dst[1] = __floats2half2_rn(v.z, v.w);
        }
        for (int i = tid; i < 2 * 8 * K2_WSTRIDE; i += 256)
            Hbuf[i] = __ushort_as_half(0);
        __syncthreads();

        // register-resident A fragments (W_hh): 16 ktiles x 2 mtiles x 4
        unsigned afr[16][2][4];
#pragma unroll
        for (int kt = 0; kt < 16; kt++)
#pragma unroll
            for (int mt = 0; mt < 2; mt++) {
                int m  = ms + mt * 16;
                int kq = kt * 16 + 2 * cq;
                afr[kt][mt][0] = *reinterpret_cast<const unsigned*>(&Wsm[m + r][kq]);
                afr[kt][mt][1] = *reinterpret_cast<const unsigned*>(&Wsm[m + r + 8][kq]);
                afr[kt][mt][2] = *reinterpret_cast<const unsigned*>(&Wsm[m + r][kq + 8]);
                afr[kt][mt][3] = *reinterpret_cast<const unsigned*>(&Wsm[m + r + 8][kq + 8]);
            }

        const unsigned hbase = (unsigned)__cvta_generic_to_shared(Hbuf);
        const unsigned laneoffB = (unsigned)((lane & 7) * K2_WSTRIDE + ((lane >> 3) & 1) * 8);

        // tid0 flow-control state: flags [0, ready) confirmed
        int ready = 0, done = 0;

        // confirm flags 0..1 before prefetching pre[0] and pre[1]
        if (tid == 0) {
            while (ready < 2) {
                int lim = 16;
                int v[16];
#pragma unroll
                for (int i = 0; i < 16; i++) v[i] = ld_relaxed(&g_flag[ready + i]);
                int cnt = 0;
#pragma unroll
                for (int i = 0; i < 16; i++) if (v[i] && cnt == i) cnt = i + 1;
                ready += cnt;
                (void)lim;
                if (ready < 2) __nanosleep(64);
            }
            asm volatile("fence.acq_rel.gpu;" ::: "memory");
        }
        __syncthreads();

        // stage pre[0] into Pstage[0] (one 16B LDG per thread, coalesced)
        {
            uint4 v = *(reinterpret_cast<const uint4*>(g_pre + ((size_t)0 * BATCH + b0 + wid) * HID) + lane);
            *reinterpret_cast<uint4*>(Pstage + (0 * 8 + wid) * PSTRIDE + lane * 8) = v;
        }
        __syncthreads();

        int cur = 0;
        for (int t = 0; t < SEQ_T; t++) {
            // issue next step's pre load early (latency hidden by mma phase)
            const int tp = t + 1;
            uint4 pv;
            const bool doPre = (tp < SEQ_T);
            if (doPre)
                pv = *(reinterpret_cast<const uint4*>(g_pre + ((size_t)tp * BATCH + b0 + wid) * HID) + lane);

            // 4 accumulator chains: [mt][parity]
            float c[2][2][4];
#pragma unroll
            for (int mt = 0; mt < 2; mt++)
#pragma unroll
                for (int p = 0; p < 2; p++)
#pragma unroll
                    for (int q = 0; q < 4; q++) c[mt][p][q] = 0.0f;

            const unsigned hb = hbase + (unsigned)(cur * 8 * K2_WSTRIDE) * 2u + laneoffB * 2u;
            unsigned bf0[2], bf1[2];
            ldsm2(bf0[0], bf1[0], hb);
#pragma unroll
            for (int kt = 0; kt < 16; kt++) {
                if (kt < 15) ldsm2(bf0[(kt + 1) & 1], bf1[(kt + 1) & 1], hb + (kt + 1) * 32u);
                const int p = kt & 1;
                mma16816(c[0][p], afr[kt][0][0], afr[kt][0][1], afr[kt][0][2], afr[kt][0][3], bf0[p], bf1[p]);
                mma16816(c[1][p], afr[kt][1][0], afr[kt][1][1], afr[kt][1][2], afr[kt][1][3], bf0[p], bf1[p]);
            }

            // park the prefetched pre[t+1] into its stage buffer
            if (doPre)
                *reinterpret_cast<uint4*>(Pstage + ((tp & 1) * 8 + wid) * PSTRIDE + lane * 8) = pv;

            // epilogue: h_new = tanh(c + pre[t]), pre read from stage (t&1)
            const __half* pc = Pstage + (t & 1) * 8 * PSTRIDE;
            __half* hn = Hbuf + (cur ^ 1) * 8 * K2_WSTRIDE;
            const bool last = (t == SEQ_T - 1);
#pragma unroll
            for (int mt = 0; mt < 2; mt++) {
                int m = ms + mt * 16;
#pragma unroll
                for (int q = 0; q < 4; q++) {
                    int hid = m + r + (q >> 1) * 8;
                    int b   = 2 * cq + (q & 1);
                    float v = (c[mt][0][q] + c[mt][1][q]) + __half2float(pc[b * PSTRIDE + hid]);
                    float y = last ? tanh_fast(v) : tanh_approx(v);
                    hn[b * K2_WSTRIDE + hid] = __float2half_rn(y);
                    if (last) g_hT[(size_t)(b0 + b) * HID + hid] = y;
                }
            }

            // flow control: confirm flag[t+2] (needed by next step's prefetch)
            if (tid == 0 && !done) {
                const int target = t + 2;
                if (target < SEQ_T && ready <= target) {
                    if (ld_acquire(&g_pre_done)) {
                        done = 1;
                    } else {
                        while (ready <= target) {
                            int lim = SEQ_T - ready; if (lim > 16) lim = 16;
                            int v[16];
#pragma unroll
                            for (int i = 0; i < 16; i++)
                                v[i] = (i < lim) ? ld_relaxed(&g_flag[ready + i]) : 0;
                            int cnt = 0;
#pragma unroll
                            for (int i = 0; i < 16; i++)
                                if (i < lim && v[i] && cnt == i) cnt = i + 1;
                            ready += cnt;
                            if (ready <= target) __nanosleep(64);
                        }
                        asm volatile("fence.acq_rel.gpu;" ::: "memory");
                    }
                }
            }
            cur ^= 1;
            __syncthreads();
        }
    } else {
        // =================== pre producer role ===================
        __half (*Asm)[K1_ASTRIDE] = reinterpret_cast<__half(*)[K1_ASTRIDE]>(smem);
        __half (*Bsm)[K1_ASTRIDE] = reinterpret_cast<__half(*)[K1_ASTRIDE]>(smem + 128 * K1_ASTRIDE * 2);
        float* bias = reinterpret_cast<float*>(smem + (128 + 256) * K1_ASTRIDE * 2);
        __shared__ int s_vb;

        const int wm = wid & 1;
        const int wn = wid >> 1;

        bias[tid] = b_ih[tid] + b_hh[tid];
        for (int i = tid; i < 256 * 128 / 4; i += 256) {
            int n  = i >> 5;
            int k4 = i & 31;
            float4 v = reinterpret_cast<const float4*>(W_ih)[i];
            __half2* dst = reinterpret_cast<__half2*>(&Bsm[n][k4 * 4]);
            dst[0] = __floats2half2_rn(v.x, v.y);
            dst[1] = __floats2half2_rn(v.z, v.w);
        }

        while (true) {
            __syncthreads();
            if (tid == 0) s_vb = atomicAdd(&g_wq, 1);
            __syncthreads();
            const int vb = s_vb;
            if (vb >= N_VBLK) break;

            for (int it = 0; it < 4; it++) {
                const int i0 = (vb * 4 + it) * 128;
                __syncthreads();  // protect Asm reuse
                {
                    int tok = tid >> 1, hf = tid & 1;
                    int gi = i0 + tok;
                    int t = gi >> 8;
                    int b = gi & 255;
                    int idx = load_index(xw, b * SEQ_T + t);
                    const float4* src = reinterpret_cast<const float4*>(emb + (size_t)idx * EMB + hf * 64);
                    __half2* dst = reinterpret_cast<__half2*>(&Asm[tok][hf * 64]);
#pragma unroll
                    for (int q = 0; q < 16; q++) {
                        float4 v = src[q];
                        dst[q * 2 + 0] = __floats2half2_rn(v.x, v.y);
                        dst[q * 2 + 1] = __floats2half2_rn(v.z, v.w);
                    }
                }
                __syncthreads();

                float c[4][8][4];
#pragma unroll
                for (int mt = 0; mt < 4; mt++)
#pragma unroll
                    for (int nt = 0; nt < 8; nt++)
#pragma unroll
                        for (int q = 0; q < 4; q++) c[mt][nt][q] = 0.0f;

#pragma unroll
                for (int kt = 0; kt < 8; kt++) {
                    unsigned a[4][4];
#pragma unroll
                    for (int mt = 0; mt < 4; mt++) {
                        int row = wm * 64 + mt * 16;
                        int k0 = kt * 16 + 2 * cq;
                        a[mt][0] = *reinterpret_cast<const unsigned*>(&Asm[row + r][k0]);
                        a[mt][1] = *reinterpret_cast<const unsigned*>(&Asm[row + r + 8][k0]);
                        a[mt][2] = *reinterpret_cast<const unsigned*>(&Asm[row + r][k0 + 8]);
                        a[mt][3] = *reinterpret_cast<const unsigned*>(&Asm[row + r + 8][k0 + 8]);
                    }
#pragma unroll
                    for (int nt = 0; nt < 8; nt++) {
                        int n = wn * 64 + nt * 8 + r;
                        int k0 = kt * 16 + 2 * cq;
                        unsigned b0 = *reinterpret_cast<const unsigned*>(&Bsm[n][k0]);
                        unsigned b1 = *reinterpret_cast<const unsigned*>(&Bsm[n][k0 + 8]);
#pragma unroll
                        for (int mt = 0; mt < 4; mt++)
                            mma16816(c[mt][nt], a[mt][0], a[mt][1], a[mt][2], a[mt][3], b0, b1);
                    }
                }

#pragma unroll
                for (int mt = 0; mt < 4; mt++) {
#pragma unroll
                    for (int nt = 0; nt < 8; nt++) {
                        int row = i0 + wm * 64 + mt * 16 + r;
                        int col = wn * 64 + nt * 8 + 2 * cq;
                        float bx = bias[col], by = bias[col + 1];
                        *reinterpret_cast<__half2*>(&g_pre[(size_t)row * HID + col]) =
                            __floats2half2_rn(c[mt][nt][0] + bx, c[mt][nt][1] + by);
                        *reinterpret_cast<__half2*>(&g_pre[(size_t)(row + 8) * HID + col]) =
                            __floats2half2_rn(c[mt][nt][2] + bx, c[mt][nt][3] + by);
                    }
                }

                if (it == 1 || it == 3) {
                    // publish timestep 2*vb + (it>>1)
                    __threadfence();
                    __syncthreads();
                    if (tid == 0) {
                        st_release(&g_flag[2 * vb + (it >> 1)], 1);
                        int done = atomicAdd(&g_vb_done, (it == 3) ? 1 : 0);
                        if (it == 3 && done + 1 == N_VBLK) st_release(&g_pre_done, 1);
                    }
                }
            }
        }
    }
}

// ---------------------------------------------------------------------------
// Kernel 3: y = hT @ Wp^T + bp, layernorm over OUT=128.
// grid 256, block 256: 2 threads per output column split the k-sum.
// ---------------------------------------------------------------------------
__global__ __launch_bounds__(256) void k_head(const float* __restrict__ Wp,
                                              const float* __restrict__ bp,
                                              const float* __restrict__ gamma,
                                              const float* __restrict__ beta,
                                              float* __restrict__ out) {
    const int b = blockIdx.x;
    const int o = threadIdx.x & 127;
    const int half = threadIdx.x >> 7;
    const int lane = threadIdx.x & 31, wid = threadIdx.x >> 5;

    __shared__ float part[128];
    __shared__ float r1[4], r2[4];

    const float* h = g_hT + (size_t)b * HID + half * 128;
    const float* w = Wp + (size_t)o * HID + half * 128;
    float s = 0.0f;
#pragma unroll 8
    for (int k = 0; k < 128; k += 4) {
        float4 hv = *reinterpret_cast<const float4*>(h + k);
        float4 wv = *reinterpret_cast<const float4*>(w + k);
        s += hv.x * wv.x + hv.y * wv.y + hv.z * wv.z + hv.w * wv.w;
    }
    if (half == 1) part[o] = s;
    __syncthreads();

    if (half == 0) {
        float y = s + part[o] + bp[o];
        float s1 = y, s2 = y * y;
#pragma unroll
        for (int off = 16; off > 0; off >>= 1) {
            s1 += __shfl_down_sync(0xffffffffu, s1, off);
            s2 += __shfl_down_sync(0xffffffffu, s2, off);
        }
        if (lane == 0) { r1[wid] = s1; r2[wid] = s2; }
        __syncthreads();
        float S1 = r1[0] + r1[1] + r1[2] + r1[3];
        float S2 = r2[0] + r2[1] + r2[2] + r2[3];
        float mu = S1 * (1.0f / OUT_N);
        float var = S2 * (1.0f / OUT_N) - mu * mu;
        float inv = rsqrtf(var + 1e-5f);
        out[(size_t)b * OUT_N + o] = (y - mu) * inv * gamma[o] + beta[o];
    }
}

// ---------------------------------------------------------------------------
extern "C" void kernel_launch(void* const* d_in, const int* in_sizes, int n_in,
                              void* d_out, int out_size) {
    const unsigned* xw = (const unsigned*)d_in[0];
    const float* emb   = (const float*)d_in[1];
    const float* W_ih  = (const float*)d_in[2];
    const float* W_hh  = (const float*)d_in[3];
    const float* b_ih  = (const float*)d_in[4];
    const float* b_hh  = (const float*)d_in[5];
    const float* Wp    = (const float*)d_in[6];
    const float* bp    = (const float*)d_in[7];
    const float* gamma = (const float*)d_in[8];
    const float* beta  = (const float*)d_in[9];
    float* out = (float*)d_out;

    cudaFuncSetAttribute(k_main, cudaFuncAttributeMaxDynamicSharedMemorySize, FUSED_SMEM_BYTES);

    k_detect_x64<<<1, 256>>>(xw);
    k_main<<<N_RNN_CTAS + N_PRE_CTAS, 256, FUSED_SMEM_BYTES>>>(xw, emb, W_ih, W_hh, b_ih, b_hh);
    k_head<<<256, 256>>>(Wp, bp, gamma, beta, out);
}

// round 10
// speedup vs baseline: 1.2788x; 1.2788x over previous
#include <cuda_runtime.h>
#include <cuda_fp16.h>
#include <cstdint>

// Problem constants
#define VOCAB 131072
#define EMB   128
#define HID   256
#define OUT_N 128
#define BATCH 256
#define SEQ_T 512

#define N_RNN_CTAS 32
#define N_PRE_CTAS 116
#define N_VBLK     256   // virtual pre-blocks (512 tokens each)

// Scratch (device globals; no allocations allowed)
__device__ __half g_pre[(size_t)SEQ_T * BATCH * HID];  // [T][B][HID] fp16, includes b_ih+b_hh
__device__ float  g_hT[BATCH * HID];                   // final hidden state fp32
__device__ int    g_x_is64;                            // 1 if x buffer is int64, else 0
__device__ int    g_flag[SEQ_T];                       // pre[t] ready flags
__device__ int    g_wq;                                // work-steal queue head
__device__ int    g_vb_done;                           // completed virtual blocks
__device__ int    g_pre_done;                          // all pre work finished

// ---------------------------------------------------------------------------
__device__ __forceinline__ void mma16816(float c[4],
                                         unsigned a0, unsigned a1, unsigned a2, unsigned a3,
                                         unsigned b0, unsigned b1) {
    asm volatile(
        "mma.sync.aligned.m16n8k16.row.col.f32.f16.f16.f32 "
        "{%0,%1,%2,%3}, {%4,%5,%6,%7}, {%8,%9}, {%0,%1,%2,%3};\n"
        : "+f"(c[0]), "+f"(c[1]), "+f"(c[2]), "+f"(c[3])
        : "r"(a0), "r"(a1), "r"(a2), "r"(a3), "r"(b0), "r"(b1));
}

__device__ __forceinline__ void ldsm2(unsigned& b0, unsigned& b1, unsigned addr) {
    asm volatile("ldmatrix.sync.aligned.m8n8.x2.shared.b16 {%0,%1}, [%2];"
                 : "=r"(b0), "=r"(b1)
                 : "r"(addr));
}

__device__ __forceinline__ float tanh_approx(float x) {
    float y;
    asm("tanh.approx.f32 %0, %1;" : "=f"(y) : "f"(x));
    return y;
}

// accurate tanh (final step only): 1 - 2/(e^{2x}+1)
__device__ __forceinline__ float tanh_fast(float x) {
    float xx = fminf(fmaxf(x, -15.0f), 15.0f);
    float e = __expf(xx + xx);
    float d = e + 1.0f;
    float r = __uint_as_float(0x7EF311C3u - __float_as_uint(d));
    r = r * (2.0f - d * r);
    r = r * (2.0f - d * r);
    return fmaf(-2.0f, r, 1.0f);
}

__device__ __forceinline__ int ld_acquire(const int* p) {
    int v;
    asm volatile("ld.acquire.gpu.b32 %0, [%1];" : "=r"(v) : "l"(p) : "memory");
    return v;
}
__device__ __forceinline__ int ld_relaxed(const int* p) {
    int v;
    asm volatile("ld.relaxed.gpu.b32 %0, [%1];" : "=r"(v) : "l"(p) : "memory");
    return v;
}
__device__ __forceinline__ void st_release(int* p, int v) {
    asm volatile("st.release.gpu.b32 [%0], %1;" :: "l"(p), "r"(v) : "memory");
}

// ---------------------------------------------------------------------------
// Kernel 0: detect x dtype + reset producer/consumer state.
// Reads odd words 1..4095 (first 16KB region — in-bounds for both layouts).
// ---------------------------------------------------------------------------
__global__ void k_detect_x64(const unsigned* __restrict__ xw) {
    __shared__ int s_any;
    if (threadIdx.x == 0) s_any = 0;
    __syncthreads();
    unsigned acc = 0;
    for (int i = threadIdx.x; i < 2048; i += 256)
        acc |= xw[2 * i + 1];
    if (acc) atomicOr(&s_any, 1);
    for (int i = threadIdx.x; i < SEQ_T; i += 256) g_flag[i] = 0;
    __syncthreads();
    if (threadIdx.x == 0) {
        g_x_is64 = (s_any == 0) ? 1 : 0;
        g_wq = 0; g_vb_done = 0; g_pre_done = 0;
    }
}

__device__ __forceinline__ int load_index(const unsigned* xw, int pos) {
    return (int)(g_x_is64 ? xw[2 * pos] : xw[pos]);
}

// ---------------------------------------------------------------------------
// Fused kernel: grid 148. CTAs 0..31: RNN consumers (8 batch rows each).
// CTAs 32..147: pre producers (work-steal 256 vblocks, publish flags).
// ---------------------------------------------------------------------------
#define K1_ASTRIDE 136
#define K2_WSTRIDE 264
#define PSTRIDE    264
#define FUSED_SMEM_BYTES ((256 * K2_WSTRIDE + 2 * 8 * K2_WSTRIDE + 2 * 8 * PSTRIDE) * 2)

__global__ __launch_bounds__(256, 1) void k_main(const unsigned* __restrict__ xw,
                                                 const float* __restrict__ emb,
                                                 const float* __restrict__ W_ih,
                                                 const float* __restrict__ W_hh,
                                                 const float* __restrict__ b_ih,
                                                 const float* __restrict__ b_hh) {
    extern __shared__ char smem[];
    const int tid  = threadIdx.x;
    const int wid  = tid >> 5;
    const int lane = tid & 31;
    const int r    = lane >> 2;
    const int cq   = lane & 3;

    if (blockIdx.x < N_RNN_CTAS) {
        // =================== RNN consumer role ===================
        __half (*Wsm)[K2_WSTRIDE] = reinterpret_cast<__half(*)[K2_WSTRIDE]>(smem);
        __half* Hbuf   = reinterpret_cast<__half*>(smem + 256 * K2_WSTRIDE * 2);
        __half* Pstage = Hbuf + 2 * 8 * K2_WSTRIDE;   // [2][8][PSTRIDE]

        const int ms = wid * 32;
        const int b0 = blockIdx.x * 8;

        for (int i = tid; i < 256 * 256 / 4; i += 256) {
            int m  = i >> 6;
            int k4 = i & 63;
            float4 v = reinterpret_cast<const float4*>(W_hh)[i];
            __half2* dst = reinterpret_cast<__half2*>(&Wsm[m][k4 * 4]);
            dst[0] = __floats2half2_rn(v.x, v.y);
            dst[1] = __floats2half2_rn(v.z, v.w);
        }
        for (int i = tid; i < 2 * 8 * K2_WSTRIDE; i += 256)
            Hbuf[i] = __ushort_as_half(0);
        __syncthreads();

        // register-resident A fragments (W_hh): 16 ktiles x 2 mtiles x 4
        unsigned afr[16][2][4];
#pragma unroll
        for (int kt = 0; kt < 16; kt++)
#pragma unroll
            for (int mt = 0; mt < 2; mt++) {
                int m  = ms + mt * 16;
                int kq = kt * 16 + 2 * cq;
                afr[kt][mt][0] = *reinterpret_cast<const unsigned*>(&Wsm[m + r][kq]);
                afr[kt][mt][1] = *reinterpret_cast<const unsigned*>(&Wsm[m + r + 8][kq]);
                afr[kt][mt][2] = *reinterpret_cast<const unsigned*>(&Wsm[m + r][kq + 8]);
                afr[kt][mt][3] = *reinterpret_cast<const unsigned*>(&Wsm[m + r + 8][kq + 8]);
            }

        const unsigned hbase = (unsigned)__cvta_generic_to_shared(Hbuf);
        const unsigned laneoffB = (unsigned)((lane & 7) * K2_WSTRIDE + ((lane >> 3) & 1) * 8);

        // tid0 flow-control: flags [0, ready) confirmed; need 0..2 up front
        int ready = 0, done = 0;
        if (tid == 0) {
            while (ready < 3) {
                int lim = SEQ_T - ready; if (lim > 16) lim = 16;
                int v[16];
#pragma unroll
                for (int i = 0; i < 16; i++)
                    v[i] = (i < lim) ? ld_relaxed(&g_flag[ready + i]) : 0;
                int cnt = 0;
#pragma unroll
                for (int i = 0; i < 16; i++)
                    if (i < lim && v[i] && cnt == i) cnt = i + 1;
                ready += cnt;
                if (ready < 3) __nanosleep(64);
            }
            asm volatile("fence.acq_rel.gpu;" ::: "memory");
        }
        __syncthreads();

        // prologue: stage pre[0] into Pstage[0]; hold pre[1] in registers
        {
            uint4 v0 = *(reinterpret_cast<const uint4*>(g_pre + ((size_t)0 * BATCH + b0 + wid) * HID) + lane);
            *reinterpret_cast<uint4*>(Pstage + (0 * 8 + wid) * PSTRIDE + lane * 8) = v0;
        }
        uint4 pv_prev = *(reinterpret_cast<const uint4*>(g_pre + ((size_t)1 * BATCH + b0 + wid) * HID) + lane);
        __syncthreads();

        int cur = 0;
        for (int t = 0; t < SEQ_T; t++) {
            // top of step: read this step's pre from stage (written >=1 step ago)
            const __half* pc = Pstage + (t & 1) * 8 * PSTRIDE;
            __half phh[2][4];
#pragma unroll
            for (int mt = 0; mt < 2; mt++) {
                int m = ms + mt * 16;
#pragma unroll
                for (int q = 0; q < 4; q++) {
                    int hid = m + r + (q >> 1) * 8;
                    int b   = 2 * cq + (q & 1);
                    phh[mt][q] = pc[b * PSTRIDE + hid];
                }
            }

            // issue LDG for pre[t+2] (consumed by STS at end of step t+1 —
            // ~1.5 steps of latency budget)
            const bool doPre2 = (t + 2 < SEQ_T);
            uint4 pv;
            if (doPre2)
                pv = *(reinterpret_cast<const uint4*>(g_pre + ((size_t)(t + 2) * BATCH + b0 + wid) * HID) + lane);

            // 4 accumulator chains: [mt][parity]
            float c[2][2][4];
#pragma unroll
            for (int mt = 0; mt < 2; mt++)
#pragma unroll
                for (int p = 0; p < 2; p++)
#pragma unroll
                    for (int q = 0; q < 4; q++) c[mt][p][q] = 0.0f;

            const unsigned hb = hbase + (unsigned)(cur * 8 * K2_WSTRIDE) * 2u + laneoffB * 2u;
            unsigned bf0[2], bf1[2];
            ldsm2(bf0[0], bf1[0], hb);
#pragma unroll
            for (int kt = 0; kt < 16; kt++) {
                if (kt < 15) ldsm2(bf0[(kt + 1) & 1], bf1[(kt + 1) & 1], hb + (kt + 1) * 32u);
                const int p = kt & 1;
                mma16816(c[0][p], afr[kt][0][0], afr[kt][0][1], afr[kt][0][2], afr[kt][0][3], bf0[p], bf1[p]);
                mma16816(c[1][p], afr[kt][1][0], afr[kt][1][1], afr[kt][1][2], afr[kt][1][3], bf0[p], bf1[p]);
            }

            // park pre[t+1] (register-resident since step t-1) into its stage
            if (t + 1 < SEQ_T)
                *reinterpret_cast<uint4*>(Pstage + (((t + 1) & 1) * 8 + wid) * PSTRIDE + lane * 8) = pv_prev;
            if (doPre2) pv_prev = pv;

            // epilogue: h_new = tanh(c + pre[t])
            __half* hn = Hbuf + (cur ^ 1) * 8 * K2_WSTRIDE;
            const bool last = (t == SEQ_T - 1);
#pragma unroll
            for (int mt = 0; mt < 2; mt++) {
                int m = ms + mt * 16;
#pragma unroll
                for (int q = 0; q < 4; q++) {
                    int hid = m + r + (q >> 1) * 8;
                    int b   = 2 * cq + (q & 1);
                    float v = (c[mt][0][q] + c[mt][1][q]) + __half2float(phh[mt][q]);
                    float y = last ? tanh_fast(v) : tanh_approx(v);
                    hn[b * K2_WSTRIDE + hid] = __float2half_rn(y);
                    if (last) g_hT[(size_t)(b0 + b) * HID + hid] = y;
                }
            }

            // flow control: confirm flag[t+3] (needed by step t+1's LDG of pre[t+3])
            if (tid == 0 && !done) {
                const int target = t + 3;
                if (target < SEQ_T && ready <= target) {
                    if (ld_acquire(&g_pre_done)) {
                        done = 1;
                    } else {
                        while (ready <= target) {
                            int lim = SEQ_T - ready; if (lim > 16) lim = 16;
                            int v[16];
#pragma unroll
                            for (int i = 0; i < 16; i++)
                                v[i] = (i < lim) ? ld_relaxed(&g_flag[ready + i]) : 0;
                            int cnt = 0;
#pragma unroll
                            for (int i = 0; i < 16; i++)
                                if (i < lim && v[i] && cnt == i) cnt = i + 1;
                            ready += cnt;
                            if (ready <= target) __nanosleep(64);
                        }
                        asm volatile("fence.acq_rel.gpu;" ::: "memory");
                    }
                }
            }
            cur ^= 1;
            __syncthreads();
        }
    } else {
        // =================== pre producer role ===================
        __half (*Asm)[K1_ASTRIDE] = reinterpret_cast<__half(*)[K1_ASTRIDE]>(smem);
        __half (*Bsm)[K1_ASTRIDE] = reinterpret_cast<__half(*)[K1_ASTRIDE]>(smem + 128 * K1_ASTRIDE * 2);
        float* bias = reinterpret_cast<float*>(smem + (128 + 256) * K1_ASTRIDE * 2);
        __shared__ int s_vb;

        const int wm = wid & 1;
        const int wn = wid >> 1;

        bias[tid] = b_ih[tid] + b_hh[tid];
        for (int i = tid; i < 256 * 128 / 4; i += 256) {
            int n  = i >> 5;
            int k4 = i & 31;
            float4 v = reinterpret_cast<const float4*>(W_ih)[i];
            __half2* dst = reinterpret_cast<__half2*>(&Bsm[n][k4 * 4]);
            dst[0] = __floats2half2_rn(v.x, v.y);
            dst[1] = __floats2half2_rn(v.z, v.w);
        }

        while (true) {
            __syncthreads();
            if (tid == 0) s_vb = atomicAdd(&g_wq, 1);
            __syncthreads();
            const int vb = s_vb;
            if (vb >= N_VBLK) break;

            for (int it = 0; it < 4; it++) {
                const int i0 = (vb * 4 + it) * 128;
                __syncthreads();  // protect Asm reuse
                {
                    int tok = tid >> 1, hf = tid & 1;
                    int gi = i0 + tok;
                    int t = gi >> 8;
                    int b = gi & 255;
                    int idx = load_index(xw, b * SEQ_T + t);
                    const float4* src = reinterpret_cast<const float4*>(emb + (size_t)idx * EMB + hf * 64);
                    __half2* dst = reinterpret_cast<__half2*>(&Asm[tok][hf * 64]);
#pragma unroll
                    for (int q = 0; q < 16; q++) {
                        float4 v = src[q];
                        dst[q * 2 + 0] = __floats2half2_rn(v.x, v.y);
                        dst[q * 2 + 1] = __floats2half2_rn(v.z, v.w);
                    }
                }
                __syncthreads();

                float c[4][8][4];
#pragma unroll
                for (int mt = 0; mt < 4; mt++)
#pragma unroll
                    for (int nt = 0; nt < 8; nt++)
#pragma unroll
                        for (int q = 0; q < 4; q++) c[mt][nt][q] = 0.0f;

#pragma unroll
                for (int kt = 0; kt < 8; kt++) {
                    unsigned a[4][4];
#pragma unroll
                    for (int mt = 0; mt < 4; mt++) {
                        int row = wm * 64 + mt * 16;
                        int k0 = kt * 16 + 2 * cq;
                        a[mt][0] = *reinterpret_cast<const unsigned*>(&Asm[row + r][k0]);
                        a[mt][1] = *reinterpret_cast<const unsigned*>(&Asm[row + r + 8][k0]);
                        a[mt][2] = *reinterpret_cast<const unsigned*>(&Asm[row + r][k0 + 8]);
                        a[mt][3] = *reinterpret_cast<const unsigned*>(&Asm[row + r + 8][k0 + 8]);
                    }
#pragma unroll
                    for (int nt = 0; nt < 8; nt++) {
                        int n = wn * 64 + nt * 8 + r;
                        int k0 = kt * 16 + 2 * cq;
                        unsigned b0 = *reinterpret_cast<const unsigned*>(&Bsm[n][k0]);
                        unsigned b1 = *reinterpret_cast<const unsigned*>(&Bsm[n][k0 + 8]);
#pragma unroll
                        for (int mt = 0; mt < 4; mt++)
                            mma16816(c[mt][nt], a[mt][0], a[mt][1], a[mt][2], a[mt][3], b0, b1);
                    }
                }

#pragma unroll
                for (int mt = 0; mt < 4; mt++) {
#pragma unroll
                    for (int nt = 0; nt < 8; nt++) {
                        int row = i0 + wm * 64 + mt * 16 + r;
                        int col = wn * 64 + nt * 8 + 2 * cq;
                        float bx = bias[col], by = bias[col + 1];
                        *reinterpret_cast<__half2*>(&g_pre[(size_t)row * HID + col]) =
                            __floats2half2_rn(c[mt][nt][0] + bx, c[mt][nt][1] + by);
                        *reinterpret_cast<__half2*>(&g_pre[(size_t)(row + 8) * HID + col]) =
                            __floats2half2_rn(c[mt][nt][2] + bx, c[mt][nt][3] + by);
                    }
                }

                if (it == 1 || it == 3) {
                    // publish timestep 2*vb + (it>>1)
                    __threadfence();
                    __syncthreads();
                    if (tid == 0) {
                        st_release(&g_flag[2 * vb + (it >> 1)], 1);
                        int done = atomicAdd(&g_vb_done, (it == 3) ? 1 : 0);
                        if (it == 3 && done + 1 == N_VBLK) st_release(&g_pre_done, 1);
                    }
                }
            }
        }
    }
}

// ---------------------------------------------------------------------------
// Kernel 3: y = hT @ Wp^T + bp, layernorm over OUT=128.
// grid 256, block 256: 2 threads per output column split the k-sum.
// ---------------------------------------------------------------------------
__global__ __launch_bounds__(256) void k_head(const float* __restrict__ Wp,
                                              const float* __restrict__ bp,
                                              const float* __restrict__ gamma,
                                              const float* __restrict__ beta,
                                              float* __restrict__ out) {
    const int b = blockIdx.x;
    const int o = threadIdx.x & 127;
    const int half = threadIdx.x >> 7;
    const int lane = threadIdx.x & 31, wid = threadIdx.x >> 5;

    __shared__ float part[128];
    __shared__ float r1[4], r2[4];

    const float* h = g_hT + (size_t)b * HID + half * 128;
    const float* w = Wp + (size_t)o * HID + half * 128;
    float s = 0.0f;
#pragma unroll 8
    for (int k = 0; k < 128; k += 4) {
        float4 hv = *reinterpret_cast<const float4*>(h + k);
        float4 wv = *reinterpret_cast<const float4*>(w + k);
        s += hv.x * wv.x + hv.y * wv.y + hv.z * wv.z + hv.w * wv.w;
    }
    if (half == 1) part[o] = s;
    __syncthreads();

    if (half == 0) {
        float y = s + part[o] + bp[o];
        float s1 = y, s2 = y * y;
#pragma unroll
        for (int off = 16; off > 0; off >>= 1) {
            s1 += __shfl_down_sync(0xffffffffu, s1, off);
            s2 += __shfl_down_sync(0xffffffffu, s2, off);
        }
        if (lane == 0) { r1[wid] = s1; r2[wid] = s2; }
        __syncthreads();
        float S1 = r1[0] + r1[1] + r1[2] + r1[3];
        float S2 = r2[0] + r2[1] + r2[2] + r2[3];
        float mu = S1 * (1.0f / OUT_N);
        float var = S2 * (1.0f / OUT_N) - mu * mu;
        float inv = rsqrtf(var + 1e-5f);
        out[(size_t)b * OUT_N + o] = (y - mu) * inv * gamma[o] + beta[o];
    }
}

// ---------------------------------------------------------------------------
extern "C" void kernel_launch(void* const* d_in, const int* in_sizes, int n_in,
                              void* d_out, int out_size) {
    const unsigned* xw = (const unsigned*)d_in[0];
    const float* emb   = (const float*)d_in[1];
    const float* W_ih  = (const float*)d_in[2];
    const float* W_hh  = (const float*)d_in[3];
    const float* b_ih  = (const float*)d_in[4];
    const float* b_hh  = (const float*)d_in[5];
    const float* Wp    = (const float*)d_in[6];
    const float* bp    = (const float*)d_in[7];
    const float* gamma = (const float*)d_in[8];
    const float* beta  = (const float*)d_in[9];
    float* out = (float*)d_out;

    cudaFuncSetAttribute(k_main, cudaFuncAttributeMaxDynamicSharedMemorySize, FUSED_SMEM_BYTES);

    k_detect_x64<<<1, 256>>>(xw);
    k_main<<<N_RNN_CTAS + N_PRE_CTAS, 256, FUSED_SMEM_BYTES>>>(xw, emb, W_ih, W_hh, b_ih, b_hh);
    k_head<<<256, 256>>>(Wp, bp, gamma, beta, out);
}

// round 11
// speedup vs baseline: 1.2856x; 1.0053x over previous
#include <cuda_runtime.h>
#include <cuda_fp16.h>
#include <cstdint>

// Problem constants
#define VOCAB 131072
#define EMB   128
#define HID   256
#define OUT_N 128
#define BATCH 256
#define SEQ_T 512

#define N_RNN_CTAS 32
#define N_PRE_CTAS 116
#define N_VBLK     256   // virtual pre-blocks (512 tokens each)

// Scratch (device globals; no allocations allowed)
__device__ __half g_pre[(size_t)SEQ_T * BATCH * HID];  // [T][B][HID] fp16, includes b_ih+b_hh
__device__ int    g_x_is64;                            // 1 if x buffer is int64, else 0
__device__ int    g_flag[SEQ_T];                       // pre[t] ready flags
__device__ int    g_wq;                                // work-steal queue head
__device__ int    g_vb_done;                           // completed virtual blocks
__device__ int    g_pre_done;                          // all pre work finished

// ---------------------------------------------------------------------------
__device__ __forceinline__ void mma16816(float c[4],
                                         unsigned a0, unsigned a1, unsigned a2, unsigned a3,
                                         unsigned b0, unsigned b1) {
    asm volatile(
        "mma.sync.aligned.m16n8k16.row.col.f32.f16.f16.f32 "
        "{%0,%1,%2,%3}, {%4,%5,%6,%7}, {%8,%9}, {%0,%1,%2,%3};\n"
        : "+f"(c[0]), "+f"(c[1]), "+f"(c[2]), "+f"(c[3])
        : "r"(a0), "r"(a1), "r"(a2), "r"(a3), "r"(b0), "r"(b1));
}

__device__ __forceinline__ void ldsm2(unsigned& b0, unsigned& b1, unsigned addr) {
    asm volatile("ldmatrix.sync.aligned.m8n8.x2.shared.b16 {%0,%1}, [%2];"
                 : "=r"(b0), "=r"(b1)
                 : "r"(addr));
}

__device__ __forceinline__ float tanh_approx(float x) {
    float y;
    asm("tanh.approx.f32 %0, %1;" : "=f"(y) : "f"(x));
    return y;
}

// accurate tanh (final step only): 1 - 2/(e^{2x}+1)
__device__ __forceinline__ float tanh_fast(float x) {
    float xx = fminf(fmaxf(x, -15.0f), 15.0f);
    float e = __expf(xx + xx);
    float d = e + 1.0f;
    float r = __uint_as_float(0x7EF311C3u - __float_as_uint(d));
    r = r * (2.0f - d * r);
    r = r * (2.0f - d * r);
    return fmaf(-2.0f, r, 1.0f);
}

__device__ __forceinline__ int ld_acquire(const int* p) {
    int v;
    asm volatile("ld.acquire.gpu.b32 %0, [%1];" : "=r"(v) : "l"(p) : "memory");
    return v;
}
__device__ __forceinline__ int ld_relaxed(const int* p) {
    int v;
    asm volatile("ld.relaxed.gpu.b32 %0, [%1];" : "=r"(v) : "l"(p) : "memory");
    return v;
}
__device__ __forceinline__ void st_release(int* p, int v) {
    asm volatile("st.release.gpu.b32 [%0], %1;" :: "l"(p), "r"(v) : "memory");
}

// ---------------------------------------------------------------------------
// Kernel 0: detect x dtype + reset producer/consumer state.
// Reads odd words 1..1023 (first 4KB region — in-bounds for both layouts).
// int64-LE => high halves all zero; int32 => P(512 uniform words all 0) ~ 0.
// ---------------------------------------------------------------------------
__global__ void k_detect_x64(const unsigned* __restrict__ xw) {
    __shared__ int s_any;
    if (threadIdx.x == 0) s_any = 0;
    __syncthreads();
    unsigned acc = 0;
    for (int i = threadIdx.x; i < 512; i += 256)
        acc |= xw[2 * i + 1];
    if (acc) atomicOr(&s_any, 1);
    for (int i = threadIdx.x; i < SEQ_T; i += 256) g_flag[i] = 0;
    __syncthreads();
    if (threadIdx.x == 0) {
        g_x_is64 = (s_any == 0) ? 1 : 0;
        g_wq = 0; g_vb_done = 0; g_pre_done = 0;
    }
}

__device__ __forceinline__ int load_index(const unsigned* xw, int pos) {
    return (int)(g_x_is64 ? xw[2 * pos] : xw[pos]);
}

// ---------------------------------------------------------------------------
// Fused kernel: grid 148. CTAs 0..31: RNN consumers (8 batch rows each),
// then fused head+layernorm for their rows. CTAs 32..147: pre producers.
// ---------------------------------------------------------------------------
#define K1_ASTRIDE 136
#define K2_WSTRIDE 264
#define PSTRIDE    264
#define H8_STRIDE  258
// Wsm 135168 + Hbuf 8448 + Pstage 8448 + h8 8256(->8448 pad) = 160512
#define SM_WSM   0
#define SM_HBUF  (256 * K2_WSTRIDE * 2)                 // 135168
#define SM_PSTG  (SM_HBUF + 2 * 8 * K2_WSTRIDE * 2)     // 143616
#define SM_H8    (SM_PSTG + 2 * 8 * PSTRIDE * 2)        // 152064
#define FUSED_SMEM_BYTES (SM_H8 + 8 * H8_STRIDE * 4)    // 160320

__global__ __launch_bounds__(256, 1) void k_main(const unsigned* __restrict__ xw,
                                                 const float* __restrict__ emb,
                                                 const float* __restrict__ W_ih,
                                                 const float* __restrict__ W_hh,
                                                 const float* __restrict__ b_ih,
                                                 const float* __restrict__ b_hh,
                                                 const float* __restrict__ Wp,
                                                 const float* __restrict__ bp,
                                                 const float* __restrict__ gamma,
                                                 const float* __restrict__ beta,
                                                 float* __restrict__ out) {
    extern __shared__ char smem[];
    const int tid  = threadIdx.x;
    const int wid  = tid >> 5;
    const int lane = tid & 31;
    const int r    = lane >> 2;
    const int cq   = lane & 3;

    if (blockIdx.x < N_RNN_CTAS) {
        // =================== RNN consumer role ===================
        __half (*Wsm)[K2_WSTRIDE] = reinterpret_cast<__half(*)[K2_WSTRIDE]>(smem);
        __half* Hbuf   = reinterpret_cast<__half*>(smem + SM_HBUF);
        __half* Pstage = reinterpret_cast<__half*>(smem + SM_PSTG);
        float*  h8     = reinterpret_cast<float*>(smem + SM_H8);   // [8][H8_STRIDE]

        const int ms = wid * 32;
        const int b0 = blockIdx.x * 8;

        for (int i = tid; i < 256 * 256 / 4; i += 256) {
            int m  = i >> 6;
            int k4 = i & 63;
            float4 v = reinterpret_cast<const float4*>(W_hh)[i];
            __half2* dst = reinterpret_cast<__half2*>(&Wsm[m][k4 * 4]);
            dst[0] = __floats2half2_rn(v.x, v.y);
            dst[1] = __floats2half2_rn(v.z, v.w);
        }
        for (int i = tid; i < 2 * 8 * K2_WSTRIDE; i += 256)
            Hbuf[i] = __ushort_as_half(0);
        __syncthreads();

        // register-resident A fragments (W_hh): 16 ktiles x 2 mtiles x 4
        unsigned afr[16][2][4];
#pragma unroll
        for (int kt = 0; kt < 16; kt++)
#pragma unroll
            for (int mt = 0; mt < 2; mt++) {
                int m  = ms + mt * 16;
                int kq = kt * 16 + 2 * cq;
                afr[kt][mt][0] = *reinterpret_cast<const unsigned*>(&Wsm[m + r][kq]);
                afr[kt][mt][1] = *reinterpret_cast<const unsigned*>(&Wsm[m + r + 8][kq]);
                afr[kt][mt][2] = *reinterpret_cast<const unsigned*>(&Wsm[m + r][kq + 8]);
                afr[kt][mt][3] = *reinterpret_cast<const unsigned*>(&Wsm[m + r + 8][kq + 8]);
            }

        const unsigned hbase = (unsigned)__cvta_generic_to_shared(Hbuf);
        const unsigned laneoffB = (unsigned)((lane & 7) * K2_WSTRIDE + ((lane >> 3) & 1) * 8);

        // tid0 flow-control: flags [0, ready) confirmed; need 0..2 up front
        int ready = 0, done = 0;
        if (tid == 0) {
            while (ready < 3) {
                int lim = SEQ_T - ready; if (lim > 16) lim = 16;
                int v[16];
#pragma unroll
                for (int i = 0; i < 16; i++)
                    v[i] = (i < lim) ? ld_relaxed(&g_flag[ready + i]) : 0;
                int cnt = 0;
#pragma unroll
                for (int i = 0; i < 16; i++)
                    if (i < lim && v[i] && cnt == i) cnt = i + 1;
                ready += cnt;
                if (ready < 3) __nanosleep(64);
            }
            asm volatile("fence.acq_rel.gpu;" ::: "memory");
        }
        __syncthreads();

        // prologue: stage pre[0] into Pstage[0]; hold pre[1] in registers
        {
            uint4 v0 = *(reinterpret_cast<const uint4*>(g_pre + ((size_t)0 * BATCH + b0 + wid) * HID) + lane);
            *reinterpret_cast<uint4*>(Pstage + (0 * 8 + wid) * PSTRIDE + lane * 8) = v0;
        }
        uint4 pv_prev = *(reinterpret_cast<const uint4*>(g_pre + ((size_t)1 * BATCH + b0 + wid) * HID) + lane);
        __syncthreads();

        int cur = 0;
        for (int t = 0; t < SEQ_T; t++) {
            // this step's pre from stage (written >=1 step ago)
            const __half* pc = Pstage + (t & 1) * 8 * PSTRIDE;
            __half phh[2][4];
#pragma unroll
            for (int mt = 0; mt < 2; mt++) {
                int m = ms + mt * 16;
#pragma unroll
                for (int q = 0; q < 4; q++) {
                    int hid = m + r + (q >> 1) * 8;
                    int b   = 2 * cq + (q & 1);
                    phh[mt][q] = pc[b * PSTRIDE + hid];
                }
            }

            // issue LDG for pre[t+2] (~1.5 steps of latency budget)
            const bool doPre2 = (t + 2 < SEQ_T);
            uint4 pv;
            if (doPre2)
                pv = *(reinterpret_cast<const uint4*>(g_pre + ((size_t)(t + 2) * BATCH + b0 + wid) * HID) + lane);

            // preload ALL 16 B fragments up front (latencies overlap)
            const unsigned hb = hbase + (unsigned)(cur * 8 * K2_WSTRIDE) * 2u + laneoffB * 2u;
            unsigned bf0[16], bf1[16];
#pragma unroll
            for (int kt = 0; kt < 16; kt++)
                ldsm2(bf0[kt], bf1[kt], hb + kt * 32u);

            // 4 accumulator chains: [mt][parity]
            float c[2][2][4];
#pragma unroll
            for (int mt = 0; mt < 2; mt++)
#pragma unroll
                for (int p = 0; p < 2; p++)
#pragma unroll
                    for (int q = 0; q < 4; q++) c[mt][p][q] = 0.0f;

#pragma unroll
            for (int kt = 0; kt < 16; kt++) {
                const int p = kt & 1;
                mma16816(c[0][p], afr[kt][0][0], afr[kt][0][1], afr[kt][0][2], afr[kt][0][3], bf0[kt], bf1[kt]);
                mma16816(c[1][p], afr[kt][1][0], afr[kt][1][1], afr[kt][1][2], afr[kt][1][3], bf0[kt], bf1[kt]);
            }

            // park pre[t+1] (register-resident since step t-1) into its stage
            if (t + 1 < SEQ_T)
                *reinterpret_cast<uint4*>(Pstage + (((t + 1) & 1) * 8 + wid) * PSTRIDE + lane * 8) = pv_prev;
            if (doPre2) pv_prev = pv;

            // epilogue: h_new = tanh(c + pre[t])
            __half* hn = Hbuf + (cur ^ 1) * 8 * K2_WSTRIDE;
            const bool last = (t == SEQ_T - 1);
#pragma unroll
            for (int mt = 0; mt < 2; mt++) {
                int m = ms + mt * 16;
#pragma unroll
                for (int q = 0; q < 4; q++) {
                    int hid = m + r + (q >> 1) * 8;
                    int b   = 2 * cq + (q & 1);
                    float v = (c[mt][0][q] + c[mt][1][q]) + __half2float(phh[mt][q]);
                    if (!last) {
                        hn[b * K2_WSTRIDE + hid] = __float2half_rn(tanh_approx(v));
                    } else {
                        h8[b * H8_STRIDE + hid] = tanh_fast(v);  // fp32 for fused head
                    }
                }
            }

            // flow control: confirm flag[t+3]
            if (tid == 0 && !done) {
                const int target = t + 3;
                if (target < SEQ_T && ready <= target) {
                    if (ld_acquire(&g_pre_done)) {
                        done = 1;
                    } else {
                        while (ready <= target) {
                            int lim = SEQ_T - ready; if (lim > 16) lim = 16;
                            int v[16];
#pragma unroll
                            for (int i = 0; i < 16; i++)
                                v[i] = (i < lim) ? ld_relaxed(&g_flag[ready + i]) : 0;
                            int cnt = 0;
#pragma unroll
                            for (int i = 0; i < 16; i++)
                                if (i < lim && v[i] && cnt == i) cnt = i + 1;
                            ready += cnt;
                            if (ready <= target) __nanosleep(64);
                        }
                        asm volatile("fence.acq_rel.gpu;" ::: "memory");
                    }
                }
            }
            cur ^= 1;
            __syncthreads();
        }

        // =================== fused head + layernorm ===================
        // h8[8][H8_STRIDE] holds this CTA's final hidden rows in fp32.
        // Reuse Wsm region for Wp transposed: fp32 [k=256][130].
        float* wT = reinterpret_cast<float*>(smem);   // 256*130*4 = 133120 <= 135168
        __shared__ float part[128];
        __shared__ float rs1[4], rs2[4];

        for (int i = tid; i < OUT_N * HID / 4; i += 256) {
            int o  = i >> 6;            // 64 float4 per Wp row
            int k4 = (i & 63) * 4;
            float4 v = reinterpret_cast<const float4*>(Wp)[i];
            wT[(k4 + 0) * 130 + o] = v.x;
            wT[(k4 + 1) * 130 + o] = v.y;
            wT[(k4 + 2) * 130 + o] = v.z;
            wT[(k4 + 3) * 130 + o] = v.w;
        }
        __syncthreads();

        const int o = tid & 127;
        const int half = tid >> 7;
        float acc[8];
#pragma unroll
        for (int j = 0; j < 8; j++) acc[j] = 0.0f;
        const int kbeg = half * 128;
        for (int k = kbeg; k < kbeg + 128; k++) {
            float wv = wT[k * 130 + o];
#pragma unroll
            for (int j = 0; j < 8; j++)
                acc[j] = fmaf(h8[j * H8_STRIDE + k], wv, acc[j]);
        }

        const float bpo = bp[o], gm = gamma[o], bt = beta[o];
        const int hl = tid & 31, hw = tid >> 5;
#pragma unroll 1
        for (int j = 0; j < 8; j++) {
            if (half == 1) part[o] = acc[j];
            __syncthreads();
            if (half == 0) {
                float y = acc[j] + part[o] + bpo;
                float s1 = y, s2 = y * y;
#pragma unroll
                for (int off = 16; off > 0; off >>= 1) {
                    s1 += __shfl_down_sync(0xffffffffu, s1, off);
                    s2 += __shfl_down_sync(0xffffffffu, s2, off);
                }
                if (hl == 0) { rs1[hw] = s1; rs2[hw] = s2; }
            }
            __syncthreads();
            if (half == 0) {
                float S1 = rs1[0] + rs1[1] + rs1[2] + rs1[3];
                float S2 = rs2[0] + rs2[1] + rs2[2] + rs2[3];
                float mu = S1 * (1.0f / OUT_N);
                float var = S2 * (1.0f / OUT_N) - mu * mu;
                float inv = rsqrtf(var + 1e-5f);
                float y = acc[j] + part[o] + bpo;
                out[(size_t)(b0 + j) * OUT_N + o] = (y - mu) * inv * gm + bt;
            }
            __syncthreads();
        }
    } else {
        // =================== pre producer role ===================
        __half (*Asm)[K1_ASTRIDE] = reinterpret_cast<__half(*)[K1_ASTRIDE]>(smem);
        __half (*Bsm)[K1_ASTRIDE] = reinterpret_cast<__half(*)[K1_ASTRIDE]>(smem + 128 * K1_ASTRIDE * 2);
        float* bias = reinterpret_cast<float*>(smem + (128 + 256) * K1_ASTRIDE * 2);
        __shared__ int s_vb;

        const int wm = wid & 1;
        const int wn = wid >> 1;

        bias[tid] = b_ih[tid] + b_hh[tid];
        for (int i = tid; i < 256 * 128 / 4; i += 256) {
            int n  = i >> 5;
            int k4 = i & 31;
            float4 v = reinterpret_cast<const float4*>(W_ih)[i];
            __half2* dst = reinterpret_cast<__half2*>(&Bsm[n][k4 * 4]);
            dst[0] = __floats2half2_rn(v.x, v.y);
            dst[1] = __floats2half2_rn(v.z, v.w);
        }

        while (true) {
            __syncthreads();
            if (tid == 0) s_vb = atomicAdd(&g_wq, 1);
            __syncthreads();
            const int vb = s_vb;
            if (vb >= N_VBLK) break;

            for (int it = 0; it < 4; it++) {
                const int i0 = (vb * 4 + it) * 128;
                __syncthreads();  // protect Asm reuse
                {
                    int tok = tid >> 1, hf = tid & 1;
                    int gi = i0 + tok;
                    int t = gi >> 8;
                    int b = gi & 255;
                    int idx = load_index(xw, b * SEQ_T + t);
                    const float4* src = reinterpret_cast<const float4*>(emb + (size_t)idx * EMB + hf * 64);
                    __half2* dst = reinterpret_cast<__half2*>(&Asm[tok][hf * 64]);
#pragma unroll
                    for (int q = 0; q < 16; q++) {
                        float4 v = src[q];
                        dst[q * 2 + 0] = __floats2half2_rn(v.x, v.y);
                        dst[q * 2 + 1] = __floats2half2_rn(v.z, v.w);
                    }
                }
                __syncthreads();

                float c[4][8][4];
#pragma unroll
                for (int mt = 0; mt < 4; mt++)
#pragma unroll
                    for (int nt = 0; nt < 8; nt++)
#pragma unroll
                        for (int q = 0; q < 4; q++) c[mt][nt][q] = 0.0f;

#pragma unroll
                for (int kt = 0; kt < 8; kt++) {
                    unsigned a[4][4];
#pragma unroll
                    for (int mt = 0; mt < 4; mt++) {
                        int row = wm * 64 + mt * 16;
                        int k0 = kt * 16 + 2 * cq;
                        a[mt][0] = *reinterpret_cast<const unsigned*>(&Asm[row + r][k0]);
                        a[mt][1] = *reinterpret_cast<const unsigned*>(&Asm[row + r + 8][k0]);
                        a[mt][2] = *reinterpret_cast<const unsigned*>(&Asm[row + r][k0 + 8]);
                        a[mt][3] = *reinterpret_cast<const unsigned*>(&Asm[row + r + 8][k0 + 8]);
                    }
#pragma unroll
                    for (int nt = 0; nt < 8; nt++) {
                        int n = wn * 64 + nt * 8 + r;
                        int k0 = kt * 16 + 2 * cq;
                        unsigned b0 = *reinterpret_cast<const unsigned*>(&Bsm[n][k0]);
                        unsigned b1 = *reinterpret_cast<const unsigned*>(&Bsm[n][k0 + 8]);
#pragma unroll
                        for (int mt = 0; mt < 4; mt++)
                            mma16816(c[mt][nt], a[mt][0], a[mt][1], a[mt][2], a[mt][3], b0, b1);
                    }
                }

#pragma unroll
                for (int mt = 0; mt < 4; mt++) {
#pragma unroll
                    for (int nt = 0; nt < 8; nt++) {
                        int row = i0 + wm * 64 + mt * 16 + r;
                        int col = wn * 64 + nt * 8 + 2 * cq;
                        float bx = bias[col], by = bias[col + 1];
                        *reinterpret_cast<__half2*>(&g_pre[(size_t)row * HID + col]) =
                            __floats2half2_rn(c[mt][nt][0] + bx, c[mt][nt][1] + by);
                        *reinterpret_cast<__half2*>(&g_pre[(size_t)(row + 8) * HID + col]) =
                            __floats2half2_rn(c[mt][nt][2] + bx, c[mt][nt][3] + by);
                    }
                }

                if (it == 1 || it == 3) {
                    // publish timestep 2*vb + (it>>1)
                    __threadfence();
                    __syncthreads();
                    if (tid == 0) {
                        st_release(&g_flag[2 * vb + (it >> 1)], 1);
                        int done = atomicAdd(&g_vb_done, (it == 3) ? 1 : 0);
                        if (it == 3 && done + 1 == N_VBLK) st_release(&g_pre_done, 1);
                    }
                }
            }
        }
    }
}

// ---------------------------------------------------------------------------
extern "C" void kernel_launch(void* const* d_in, const int* in_sizes, int n_in,
                              void* d_out, int out_size) {
    const unsigned* xw = (const unsigned*)d_in[0];
    const float* emb   = (const float*)d_in[1];
    const float* W_ih  = (const float*)d_in[2];
    const float* W_hh  = (const float*)d_in[3];
    const float* b_ih  = (const float*)d_in[4];
    const float* b_hh  = (const float*)d_in[5];
    const float* Wp    = (const float*)d_in[6];
    const float* bp    = (const float*)d_in[7];
    const float* gamma = (const float*)d_in[8];
    const float* beta  = (const float*)d_in[9];
    float* out = (float*)d_out;

    cudaFuncSetAttribute(k_main, cudaFuncAttributeMaxDynamicSharedMemorySize, FUSED_SMEM_BYTES);

    k_detect_x64<<<1, 256>>>(xw);
    k_main<<<N_RNN_CTAS + N_PRE_CTAS, 256, FUSED_SMEM_BYTES>>>(
        xw, emb, W_ih, W_hh, b_ih, b_hh, Wp, bp, gamma, beta, out);
}

// round 12
// speedup vs baseline: 1.3286x; 1.0334x over previous
#include <cuda_runtime.h>
#include <cuda_fp16.h>
#include <cstdint>

// Problem constants
#define VOCAB 131072
#define EMB   128
#define HID   256
#define OUT_N 128
#define BATCH 256
#define SEQ_T 512

#define N_RNN_CTAS 32
#define N_PRE_CTAS 116
#define N_VBLK     256   // virtual pre-blocks (512 tokens each)
#define THREADS    512

// Scratch (device globals; no allocations allowed)
__device__ __half g_pre[(size_t)SEQ_T * BATCH * HID];  // [T][B][HID] fp16, includes b_ih+b_hh
__device__ int    g_x_is64;                            // 1 if x buffer is int64, else 0
__device__ int    g_flag[SEQ_T];                       // pre[t] ready flags
__device__ int    g_wq;                                // work-steal queue head
__device__ int    g_vb_done;                           // completed virtual blocks
__device__ int    g_pre_done;                          // all pre work finished

// ---------------------------------------------------------------------------
__device__ __forceinline__ void mma16816(float c[4],
                                         unsigned a0, unsigned a1, unsigned a2, unsigned a3,
                                         unsigned b0, unsigned b1) {
    asm volatile(
        "mma.sync.aligned.m16n8k16.row.col.f32.f16.f16.f32 "
        "{%0,%1,%2,%3}, {%4,%5,%6,%7}, {%8,%9}, {%0,%1,%2,%3};\n"
        : "+f"(c[0]), "+f"(c[1]), "+f"(c[2]), "+f"(c[3])
        : "r"(a0), "r"(a1), "r"(a2), "r"(a3), "r"(b0), "r"(b1));
}

__device__ __forceinline__ void ldsm2(unsigned& b0, unsigned& b1, unsigned addr) {
    asm volatile("ldmatrix.sync.aligned.m8n8.x2.shared.b16 {%0,%1}, [%2];"
                 : "=r"(b0), "=r"(b1)
                 : "r"(addr));
}

__device__ __forceinline__ float tanh_approx(float x) {
    float y;
    asm("tanh.approx.f32 %0, %1;" : "=f"(y) : "f"(x));
    return y;
}

// accurate tanh (final step only): 1 - 2/(e^{2x}+1)
__device__ __forceinline__ float tanh_fast(float x) {
    float xx = fminf(fmaxf(x, -15.0f), 15.0f);
    float e = __expf(xx + xx);
    float d = e + 1.0f;
    float r = __uint_as_float(0x7EF311C3u - __float_as_uint(d));
    r = r * (2.0f - d * r);
    r = r * (2.0f - d * r);
    return fmaf(-2.0f, r, 1.0f);
}

__device__ __forceinline__ int ld_acquire(const int* p) {
    int v;
    asm volatile("ld.acquire.gpu.b32 %0, [%1];" : "=r"(v) : "l"(p) : "memory");
    return v;
}
__device__ __forceinline__ int ld_relaxed(const int* p) {
    int v;
    asm volatile("ld.relaxed.gpu.b32 %0, [%1];" : "=r"(v) : "l"(p) : "memory");
    return v;
}
__device__ __forceinline__ void st_release(int* p, int v) {
    asm volatile("st.release.gpu.b32 [%0], %1;" :: "l"(p), "r"(v) : "memory");
}

// ---------------------------------------------------------------------------
// Kernel 0: detect x dtype + reset producer/consumer state.
// Reads odd words 1..1023 (first 4KB region — in-bounds for both layouts).
// ---------------------------------------------------------------------------
__global__ void k_detect_x64(const unsigned* __restrict__ xw) {
    __shared__ int s_any;
    if (threadIdx.x == 0) s_any = 0;
    __syncthreads();
    unsigned acc = 0;
    for (int i = threadIdx.x; i < 512; i += 256)
        acc |= xw[2 * i + 1];
    if (acc) atomicOr(&s_any, 1);
    for (int i = threadIdx.x; i < SEQ_T; i += 256) g_flag[i] = 0;
    __syncthreads();
    if (threadIdx.x == 0) {
        g_x_is64 = (s_any == 0) ? 1 : 0;
        g_wq = 0; g_vb_done = 0; g_pre_done = 0;
    }
}

__device__ __forceinline__ int load_index(const unsigned* xw, int pos) {
    return (int)(g_x_is64 ? xw[2 * pos] : xw[pos]);
}

// ---------------------------------------------------------------------------
// Fused kernel, 512 threads (16 warps). CTAs 0..31: RNN consumers (8 batch
// rows each; each warp owns an M=16 hid-out slice), then fused head+LN.
// CTAs 32..147: pre producers (work-steal vblocks, publish flags).
// ---------------------------------------------------------------------------
#define K1_ASTRIDE 136
#define K2_WSTRIDE 264
#define PSTRIDE    264
#define H8_STRIDE  258
#define SM_WSM   0
#define SM_HBUF  (256 * K2_WSTRIDE * 2)                 // 135168
#define SM_PSTG  (SM_HBUF + 2 * 8 * K2_WSTRIDE * 2)     // 143616
#define SM_H8    (SM_PSTG + 2 * 8 * PSTRIDE * 2)        // 152064
#define FUSED_SMEM_BYTES (SM_H8 + 8 * H8_STRIDE * 4)    // 160320

__global__ __launch_bounds__(THREADS, 1) void k_main(const unsigned* __restrict__ xw,
                                                     const float* __restrict__ emb,
                                                     const float* __restrict__ W_ih,
                                                     const float* __restrict__ W_hh,
                                                     const float* __restrict__ b_ih,
                                                     const float* __restrict__ b_hh,
                                                     const float* __restrict__ Wp,
                                                     const float* __restrict__ bp,
                                                     const float* __restrict__ gamma,
                                                     const float* __restrict__ beta,
                                                     float* __restrict__ out) {
    extern __shared__ char smem[];
    const int tid  = threadIdx.x;
    const int wid  = tid >> 5;
    const int lane = tid & 31;
    const int r    = lane >> 2;
    const int cq   = lane & 3;

    if (blockIdx.x < N_RNN_CTAS) {
        // =================== RNN consumer role ===================
        __half (*Wsm)[K2_WSTRIDE] = reinterpret_cast<__half(*)[K2_WSTRIDE]>(smem);
        __half* Hbuf   = reinterpret_cast<__half*>(smem + SM_HBUF);
        __half* Pstage = reinterpret_cast<__half*>(smem + SM_PSTG);
        float*  h8     = reinterpret_cast<float*>(smem + SM_H8);   // [8][H8_STRIDE]

        const int ms = wid * 16;            // this warp's M=16 hid-out slice
        const int b0 = blockIdx.x * 8;
        const bool pw = (wid < 8);          // pre-prefetch warps

        for (int i = tid; i < 256 * 256 / 4; i += THREADS) {
            int m  = i >> 6;
            int k4 = i & 63;
            float4 v = reinterpret_cast<const float4*>(W_hh)[i];
            __half2* dst = reinterpret_cast<__half2*>(&Wsm[m][k4 * 4]);
            dst[0] = __floats2half2_rn(v.x, v.y);
            dst[1] = __floats2half2_rn(v.z, v.w);
        }
        for (int i = tid; i < 2 * 8 * K2_WSTRIDE; i += THREADS)
            Hbuf[i] = __ushort_as_half(0);
        __syncthreads();

        // register-resident A fragments (W_hh): 16 ktiles x 4 regs = 64 regs
        unsigned afr[16][4];
#pragma unroll
        for (int kt = 0; kt < 16; kt++) {
            int kq = kt * 16 + 2 * cq;
            afr[kt][0] = *reinterpret_cast<const unsigned*>(&Wsm[ms + r][kq]);
            afr[kt][1] = *reinterpret_cast<const unsigned*>(&Wsm[ms + r + 8][kq]);
            afr[kt][2] = *reinterpret_cast<const unsigned*>(&Wsm[ms + r][kq + 8]);
            afr[kt][3] = *reinterpret_cast<const unsigned*>(&Wsm[ms + r + 8][kq + 8]);
        }

        const unsigned hbase = (unsigned)__cvta_generic_to_shared(Hbuf);
        const unsigned laneoffB = (unsigned)((lane & 7) * K2_WSTRIDE + ((lane >> 3) & 1) * 8);

        // tid0 flow-control: flags [0, ready) confirmed; need 0..2 up front
        int ready = 0, done = 0;
        if (tid == 0) {
            while (ready < 3) {
                int lim = SEQ_T - ready; if (lim > 16) lim = 16;
                int v[16];
#pragma unroll
                for (int i = 0; i < 16; i++)
                    v[i] = (i < lim) ? ld_relaxed(&g_flag[ready + i]) : 0;
                int cnt = 0;
#pragma unroll
                for (int i = 0; i < 16; i++)
                    if (i < lim && v[i] && cnt == i) cnt = i + 1;
                ready += cnt;
                if (ready < 3) __nanosleep(64);
            }
            asm volatile("fence.acq_rel.gpu;" ::: "memory");
        }
        __syncthreads();

        // prologue: stage pre[0]; hold pre[1] in registers (warps 0..7 only)
        uint4 pv_prev = make_uint4(0, 0, 0, 0);
        if (pw) {
            uint4 v0 = *(reinterpret_cast<const uint4*>(g_pre + ((size_t)0 * BATCH + b0 + wid) * HID) + lane);
            *reinterpret_cast<uint4*>(Pstage + (0 * 8 + wid) * PSTRIDE + lane * 8) = v0;
            pv_prev = *(reinterpret_cast<const uint4*>(g_pre + ((size_t)1 * BATCH + b0 + wid) * HID) + lane);
        }
        __syncthreads();

        int cur = 0;
        for (int t = 0; t < SEQ_T; t++) {
            // this step's pre from stage (written >=1 step ago)
            const __half* pc = Pstage + (t & 1) * 8 * PSTRIDE;
            __half phh[4];
#pragma unroll
            for (int q = 0; q < 4; q++) {
                int hid = ms + r + (q >> 1) * 8;
                int b   = 2 * cq + (q & 1);
                phh[q] = pc[b * PSTRIDE + hid];
            }

            // issue LDG for pre[t+2] (~1.5 steps of latency budget)
            const bool doPre2 = pw && (t + 2 < SEQ_T);
            uint4 pv;
            if (doPre2)
                pv = *(reinterpret_cast<const uint4*>(g_pre + ((size_t)(t + 2) * BATCH + b0 + wid) * HID) + lane);

            // mma: 16 k-tiles, 2 parity chains, ldsm ring depth 4
            const unsigned hb = hbase + (unsigned)(cur * 8 * K2_WSTRIDE) * 2u + laneoffB * 2u;
            unsigned bf0[4], bf1[4];
#pragma unroll
            for (int kt = 0; kt < 4; kt++)
                ldsm2(bf0[kt], bf1[kt], hb + kt * 32u);

            float c[2][4];
#pragma unroll
            for (int p = 0; p < 2; p++)
#pragma unroll
                for (int q = 0; q < 4; q++) c[p][q] = 0.0f;

#pragma unroll
            for (int kt = 0; kt < 16; kt++) {
                const int s = kt & 3;
                mma16816(c[kt & 1], afr[kt][0], afr[kt][1], afr[kt][2], afr[kt][3], bf0[s], bf1[s]);
                if (kt + 4 < 16) ldsm2(bf0[s], bf1[s], hb + (kt + 4) * 32u);
            }

            // park pre[t+1] (register-resident since step t-1) into its stage
            if (pw && t + 1 < SEQ_T)
                *reinterpret_cast<uint4*>(Pstage + (((t + 1) & 1) * 8 + wid) * PSTRIDE + lane * 8) = pv_prev;
            if (doPre2) pv_prev = pv;

            // epilogue: h_new = tanh(c + pre[t]), 4 values per thread
            __half* hn = Hbuf + (cur ^ 1) * 8 * K2_WSTRIDE;
            const bool last = (t == SEQ_T - 1);
#pragma unroll
            for (int q = 0; q < 4; q++) {
                int hid = ms + r + (q >> 1) * 8;
                int b   = 2 * cq + (q & 1);
                float v = (c[0][q] + c[1][q]) + __half2float(phh[q]);
                if (!last) {
                    hn[b * K2_WSTRIDE + hid] = __float2half_rn(tanh_approx(v));
                } else {
                    h8[b * H8_STRIDE + hid] = tanh_fast(v);  // fp32 for fused head
                }
            }

            // flow control: confirm flag[t+3]
            if (tid == 0 && !done) {
                const int target = t + 3;
                if (target < SEQ_T && ready <= target) {
                    if (ld_acquire(&g_pre_done)) {
                        done = 1;
                    } else {
                        while (ready <= target) {
                            int lim = SEQ_T - ready; if (lim > 16) lim = 16;
                            int v[16];
#pragma unroll
                            for (int i = 0; i < 16; i++)
                                v[i] = (i < lim) ? ld_relaxed(&g_flag[ready + i]) : 0;
                            int cnt = 0;
#pragma unroll
                            for (int i = 0; i < 16; i++)
                                if (i < lim && v[i] && cnt == i) cnt = i + 1;
                            ready += cnt;
                            if (ready <= target) __nanosleep(64);
                        }
                        asm volatile("fence.acq_rel.gpu;" ::: "memory");
                    }
                }
            }
            cur ^= 1;
            __syncthreads();
        }

        // =================== fused head + layernorm ===================
        // h8[8][H8_STRIDE] fp32. Reuse Wsm region for Wp^T fp32 [k=256][130].
        float* wT = reinterpret_cast<float*>(smem);   // 256*130*4 = 133120 <= 135168
        __shared__ float part4[3][128];
        __shared__ float rs1[4], rs2[4];

        for (int i = tid; i < OUT_N * HID / 4; i += THREADS) {
            int o  = i >> 6;            // 64 float4 per Wp row
            int k4 = (i & 63) * 4;
            float4 v = reinterpret_cast<const float4*>(Wp)[i];
            wT[(k4 + 0) * 130 + o] = v.x;
            wT[(k4 + 1) * 130 + o] = v.y;
            wT[(k4 + 2) * 130 + o] = v.z;
            wT[(k4 + 3) * 130 + o] = v.w;
        }
        __syncthreads();

        const int o = tid & 127;
        const int qq = tid >> 7;     // 0..3, each covers 64 k
        float acc[8];
#pragma unroll
        for (int j = 0; j < 8; j++) acc[j] = 0.0f;
        const int kbeg = qq * 64;
        for (int k = kbeg; k < kbeg + 64; k++) {
            float wv = wT[k * 130 + o];
#pragma unroll
            for (int j = 0; j < 8; j++)
                acc[j] = fmaf(h8[j * H8_STRIDE + k], wv, acc[j]);
        }

        const float bpo = bp[o], gm = gamma[o], bt = beta[o];
        const int hl = tid & 31, hw = tid >> 5;   // for qq==0: hw in 0..3
#pragma unroll 1
        for (int j = 0; j < 8; j++) {
            if (qq > 0) part4[qq - 1][o] = acc[j];
            __syncthreads();
            float y = 0.0f;
            if (qq == 0) {
                y = acc[j] + part4[0][o] + part4[1][o] + part4[2][o] + bpo;
                float s1 = y, s2 = y * y;
#pragma unroll
                for (int off = 16; off > 0; off >>= 1) {
                    s1 += __shfl_down_sync(0xffffffffu, s1, off);
                    s2 += __shfl_down_sync(0xffffffffu, s2, off);
                }
                if (hl == 0) { rs1[hw] = s1; rs2[hw] = s2; }
            }
            __syncthreads();
            if (qq == 0) {
                float S1 = rs1[0] + rs1[1] + rs1[2] + rs1[3];
                float S2 = rs2[0] + rs2[1] + rs2[2] + rs2[3];
                float mu = S1 * (1.0f / OUT_N);
                float var = S2 * (1.0f / OUT_N) - mu * mu;
                float inv = rsqrtf(var + 1e-5f);
                out[(size_t)(b0 + j) * OUT_N + o] = (y - mu) * inv * gm + bt;
            }
            __syncthreads();
        }
    } else {
        // =================== pre producer role (16 warps) ===================
        __half (*Asm)[K1_ASTRIDE] = reinterpret_cast<__half(*)[K1_ASTRIDE]>(smem);
        __half (*Bsm)[K1_ASTRIDE] = reinterpret_cast<__half(*)[K1_ASTRIDE]>(smem + 128 * K1_ASTRIDE * 2);
        float* bias = reinterpret_cast<float*>(smem + (128 + 256) * K1_ASTRIDE * 2);
        __shared__ int s_vb;

        const int wm = wid & 3;     // 4 warps along M (32 rows each)
        const int wn = wid >> 2;    // 4 warps along N (64 cols each)

        if (tid < 256) bias[tid] = b_ih[tid] + b_hh[tid];
        for (int i = tid; i < 256 * 128 / 4; i += THREADS) {
            int n  = i >> 5;
            int k4 = i & 31;
            float4 v = reinterpret_cast<const float4*>(W_ih)[i];
            __half2* dst = reinterpret_cast<__half2*>(&Bsm[n][k4 * 4]);
            dst[0] = __floats2half2_rn(v.x, v.y);
            dst[1] = __floats2half2_rn(v.z, v.w);
        }

        while (true) {
            __syncthreads();
            if (tid == 0) s_vb = atomicAdd(&g_wq, 1);
            __syncthreads();
            const int vb = s_vb;
            if (vb >= N_VBLK) break;

            for (int it = 0; it < 4; it++) {
                const int i0 = (vb * 4 + it) * 128;
                __syncthreads();  // protect Asm reuse
                {
                    // 4 threads per token, 32 floats each
                    int tok = tid >> 2, qp = tid & 3;
                    int gi = i0 + tok;
                    int t = gi >> 8;
                    int b = gi & 255;
                    int idx = load_index(xw, b * SEQ_T + t);
                    const float4* src = reinterpret_cast<const float4*>(emb + (size_t)idx * EMB + qp * 32);
                    __half2* dst = reinterpret_cast<__half2*>(&Asm[tok][qp * 32]);
#pragma unroll
                    for (int q = 0; q < 8; q++) {
                        float4 v = src[q];
                        dst[q * 2 + 0] = __floats2half2_rn(v.x, v.y);
                        dst[q * 2 + 1] = __floats2half2_rn(v.z, v.w);
                    }
                }
                __syncthreads();

                float c[2][8][4];
#pragma unroll
                for (int mt = 0; mt < 2; mt++)
#pragma unroll
                    for (int nt = 0; nt < 8; nt++)
#pragma unroll
                        for (int q = 0; q < 4; q++) c[mt][nt][q] = 0.0f;

#pragma unroll
                for (int kt = 0; kt < 8; kt++) {
                    unsigned a[2][4];
#pragma unroll
                    for (int mt = 0; mt < 2; mt++) {
                        int row = wm * 32 + mt * 16;
                        int k0 = kt * 16 + 2 * cq;
                        a[mt][0] = *reinterpret_cast<const unsigned*>(&Asm[row + r][k0]);
                        a[mt][1] = *reinterpret_cast<const unsigned*>(&Asm[row + r + 8][k0]);
                        a[mt][2] = *reinterpret_cast<const unsigned*>(&Asm[row + r][k0 + 8]);
                        a[mt][3] = *reinterpret_cast<const unsigned*>(&Asm[row + r + 8][k0 + 8]);
                    }
#pragma unroll
                    for (int nt = 0; nt < 8; nt++) {
                        int n = wn * 64 + nt * 8 + r;
                        int k0 = kt * 16 + 2 * cq;
                        unsigned b0 = *reinterpret_cast<const unsigned*>(&Bsm[n][k0]);
                        unsigned b1 = *reinterpret_cast<const unsigned*>(&Bsm[n][k0 + 8]);
#pragma unroll
                        for (int mt = 0; mt < 2; mt++)
                            mma16816(c[mt][nt], a[mt][0], a[mt][1], a[mt][2], a[mt][3], b0, b1);
                    }
                }

#pragma unroll
                for (int mt = 0; mt < 2; mt++) {
#pragma unroll
                    for (int nt = 0; nt < 8; nt++) {
                        int row = i0 + wm * 32 + mt * 16 + r;
                        int col = wn * 64 + nt * 8 + 2 * cq;
                        float bx = bias[col], by = bias[col + 1];
                        *reinterpret_cast<__half2*>(&g_pre[(size_t)row * HID + col]) =
                            __floats2half2_rn(c[mt][nt][0] + bx, c[mt][nt][1] + by);
                        *reinterpret_cast<__half2*>(&g_pre[(size_t)(row + 8) * HID + col]) =
                            __floats2half2_rn(c[mt][nt][2] + bx, c[mt][nt][3] + by);
                    }
                }

                if (it == 1 || it == 3) {
                    // publish timestep 2*vb + (it>>1)
                    __threadfence();
                    __syncthreads();
                    if (tid == 0) {
                        st_release(&g_flag[2 * vb + (it >> 1)], 1);
                        int done = atomicAdd(&g_vb_done, (it == 3) ? 1 : 0);
                        if (it == 3 && done + 1 == N_VBLK) st_release(&g_pre_done, 1);
                    }
                }
            }
        }
    }
}

// ---------------------------------------------------------------------------
extern "C" void kernel_launch(void* const* d_in, const int* in_sizes, int n_in,
                              void* d_out, int out_size) {
    const unsigned* xw = (const unsigned*)d_in[0];
    const float* emb   = (const float*)d_in[1];
    const float* W_ih  = (const float*)d_in[2];
    const float* W_hh  = (const float*)d_in[3];
    const float* b_ih  = (const float*)d_in[4];
    const float* b_hh  = (const float*)d_in[5];
    const float* Wp    = (const float*)d_in[6];
    const float* bp    = (const float*)d_in[7];
    const float* gamma = (const float*)d_in[8];
    const float* beta  = (const float*)d_in[9];
    float* out = (float*)d_out;

    cudaFuncSetAttribute(k_main, cudaFuncAttributeMaxDynamicSharedMemorySize, FUSED_SMEM_BYTES);

    k_detect_x64<<<1, 256>>>(xw);
    k_main<<<N_RNN_CTAS + N_PRE_CTAS, THREADS, FUSED_SMEM_BYTES>>>(
        xw, emb, W_ih, W_hh, b_ih, b_hh, Wp, bp, gamma, beta, out);
}